// round 17
// baseline (speedup 1.0000x reference)
#include <cuda_runtime.h>
#include <stdint.h>
#include <math.h>

#define BATCH 4
#define SEQ   2048
#define DIM   1024
#define MTOT  (BATCH * SEQ)   // 8192
#define SCALE 0.03125f        // 1/sqrt(1024)

// ---------------------------------------------------------------------------
// Device-global scratch (allocation-guard safe) — all fp32 (tf32-rounded)
// ---------------------------------------------------------------------------
__device__ float g_X [(size_t)MTOT * DIM];                 // rounded x [m][k]
__device__ float g_WT[(size_t)3 * DIM * DIM];              // rounded W^T [w][n][k]
__device__ float g_Q [(size_t)MTOT * DIM];                 // rounded
__device__ float g_K [(size_t)MTOT * DIM];                 // rounded
__device__ float g_V [(size_t)MTOT * DIM];                 // rounded
__device__ float g_VT[(size_t)BATCH * DIM * SEQ];          // V^T [b][d][s]
__device__ float g_S [(size_t)BATCH * SEQ * SEQ];          // raw scores
__device__ float g_P [(size_t)BATCH * SEQ * SEQ];          // rounded softmax

#define SWZ(o) ((o) ^ (((o) >> 3) & 0x70))
// K-chunk = 32 tf32 cols -> 128B rows.
// CTA tile 256x128. Stage: A (256x32, 32KB) @0, B (128x32, 16KB) @32768.
#define STAGE_BYTES 49152
#define NSTAGE 3
#define NTHREADS 512    // 16 warps: wm in [0,4) x 64 rows, wn in [0,4) x 32 cols

__device__ __forceinline__ uint32_t su32(const void* p) {
    uint32_t a;
    asm("{ .reg .u64 t; cvta.to.shared.u64 t, %1; cvt.u32.u64 %0, t; }"
        : "=r"(a) : "l"(p));
    return a;
}

__device__ __forceinline__ float totf(float v) {
    uint32_t r;
    asm("cvt.rna.tf32.f32 %0, %1;" : "=r"(r) : "f"(v));
    return __uint_as_float(r);
}

__device__ __forceinline__ void ldsm4(uint32_t* r, uint32_t addr) {
    asm volatile("ldmatrix.sync.aligned.m8n8.x4.shared.b16 {%0,%1,%2,%3}, [%4];"
                 : "=r"(r[0]), "=r"(r[1]), "=r"(r[2]), "=r"(r[3]) : "r"(addr));
}

__device__ __forceinline__ void mma_tf32(float* d, const uint32_t* a,
                                         uint32_t b0, uint32_t b1) {
    asm volatile(
        "mma.sync.aligned.m16n8k8.row.col.f32.tf32.tf32.f32 "
        "{%0,%1,%2,%3}, {%4,%5,%6,%7}, {%8,%9}, {%0,%1,%2,%3};"
        : "+f"(d[0]), "+f"(d[1]), "+f"(d[2]), "+f"(d[3])
        : "r"(a[0]), "r"(a[1]), "r"(a[2]), "r"(a[3]), "r"(b0), "r"(b1));
}

__device__ __forceinline__ void cp_commit() {
    asm volatile("cp.async.commit_group;" ::: "memory");
}
__device__ __forceinline__ void cp_wait1() {
    asm volatile("cp.async.wait_group 1;" ::: "memory");
}
__device__ __forceinline__ void cp_wait0() {
    asm volatile("cp.async.wait_group 0;" ::: "memory");
}

// Async load of an nrow x 32-col fp32 tile (128B rows, SW128) into SMEM.
// niter = nrow * 8 / NTHREADS
__device__ __forceinline__ void async_tile(uint32_t dst, const float* src,
                                           int ld, int tid, int niter) {
    #pragma unroll
    for (int t = 0; t < niter; t++) {
        const int idx = tid + t * NTHREADS;
        const int row = idx >> 3;
        const int c = idx & 7;
        const uint32_t d = dst + SWZ((uint32_t)(row * 128 + c * 16));
        asm volatile("cp.async.cg.shared.global [%0], [%1], 16;"
                     :: "r"(d), "l"(src + (size_t)row * ld + c * 4));
    }
}

// One K-chunk: A = 256x32, B = 128x32
__device__ __forceinline__ void load_chunk(uint32_t stage_base,
                                           const float* A, int lda,
                                           const float* B, int ldb,
                                           int kc, int tid) {
    async_tile(stage_base,         A + (size_t)kc * 32, lda, tid, 4);
    async_tile(stage_base + 32768, B + (size_t)kc * 32, ldb, tid, 2);
    cp_commit();
}

// ---------------------------------------------------------------------------
// Warp K-chunk compute: 64x32 warp tile, 4 k8 steps, single-pass tf32.
// Per ks: 2 B LDSM.x4 + 4 A LDSM.x4 -> 16 MMAs
// ---------------------------------------------------------------------------
__device__ __forceinline__ void compute_chunk(uint32_t stage_base,
                                              float acc[4][4][4], int lane,
                                              int wm, int wn) {
    const uint32_t a_b = stage_base;
    const uint32_t b_b = stage_base + 32768;
    const int ar = lane & 15;
    const int xo = (lane >> 4) * 16;
    #pragma unroll
    for (int ks = 0; ks < 4; ks++) {
        uint32_t B[2][4];
        #pragma unroll
        for (int p = 0; p < 2; p++)
            ldsm4(B[p], b_b + SWZ((uint32_t)((wn * 32 + p * 16 + ar) * 128 +
                                             ks * 32 + xo)));
        #pragma unroll
        for (int mt = 0; mt < 4; mt++) {
            uint32_t A[4];
            ldsm4(A, a_b + SWZ((uint32_t)((wm * 64 + mt * 16 + ar) * 128 +
                                          ks * 32 + xo)));
            #pragma unroll
            for (int nt = 0; nt < 4; nt++) {
                const int p = nt >> 1, h = nt & 1;
                mma_tf32(acc[mt][nt], A, B[p][h], B[p][2 + h]);
            }
        }
    }
}

// 3-stage pipeline, 2-deep prefetch, ONE barrier per chunk.
__device__ __forceinline__ void gemm_pipeline(uint32_t smb, int nchunks,
                                              const float* A, int lda,
                                              const float* B, int ldb,
                                              float acc[4][4][4], int tid,
                                              int lane, int wm, int wn) {
    load_chunk(smb, A, lda, B, ldb, 0, tid);
    if (1 < nchunks) load_chunk(smb + STAGE_BYTES, A, lda, B, ldb, 1, tid);
    int ld_stage = 2, cp_stage = 0;
    for (int kc = 0; kc < nchunks; kc++) {
        if (kc + 1 < nchunks) cp_wait1();
        else                  cp_wait0();
        __syncthreads();
        if (kc + 2 < nchunks) {
            load_chunk(smb + ld_stage * STAGE_BYTES, A, lda, B, ldb, kc + 2, tid);
            if (++ld_stage == NSTAGE) ld_stage = 0;
        }
        compute_chunk(smb + cp_stage * STAGE_BYTES, acc, lane, wm, wn);
        if (++cp_stage == NSTAGE) cp_stage = 0;
    }
}

// ---------------------------------------------------------------------------
// Epilogue. mode 0: plain fp32; mode 1: scores mask+scale; mode 2: tf32 round
// ---------------------------------------------------------------------------
__device__ __forceinline__ void store_acc(float acc[4][4][4], float* dst,
                                          int ld, int m0, int n0, int mode,
                                          int lane, int wm, int wn) {
    #pragma unroll
    for (int mt = 0; mt < 4; mt++)
        #pragma unroll
        for (int nt = 0; nt < 4; nt++) {
            const int row = m0 + wm * 64 + mt * 16 + (lane >> 2);
            const int col = n0 + wn * 32 + nt * 8 + (lane & 3) * 2;
            float2 v0 = {acc[mt][nt][0], acc[mt][nt][1]};
            float2 v1 = {acc[mt][nt][2], acc[mt][nt][3]};
            if (mode == 1) {
                v0.x = (col + 0 > row) ? -1e30f : v0.x * SCALE;
                v0.y = (col + 1 > row) ? -1e30f : v0.y * SCALE;
                v1.x = (col + 0 > row + 8) ? -1e30f : v1.x * SCALE;
                v1.y = (col + 1 > row + 8) ? -1e30f : v1.y * SCALE;
            } else if (mode == 2) {
                v0.x = totf(v0.x); v0.y = totf(v0.y);
                v1.x = totf(v1.x); v1.y = totf(v1.y);
            }
            *(float2*)(dst + (size_t)row * ld + col) = v0;
            *(float2*)(dst + (size_t)(row + 8) * ld + col) = v1;
        }
}

// ---------------------------------------------------------------------------
// Prep kernels
// ---------------------------------------------------------------------------
__global__ void round_x(const float4* __restrict__ x) {
    const size_t i = (size_t)blockIdx.x * blockDim.x + threadIdx.x;
    float4 v = x[i];
    v.x = totf(v.x); v.y = totf(v.y); v.z = totf(v.z); v.w = totf(v.w);
    ((float4*)g_X)[i] = v;
}

__global__ void prep_w(const float* __restrict__ Wq, const float* __restrict__ Wk,
                       const float* __restrict__ Wv) {
    __shared__ float t[32][33];
    const int w = blockIdx.z;
    const float* W = (w == 0) ? Wq : (w == 1) ? Wk : Wv;
    float* o = g_WT + (size_t)w * DIM * DIM;
    const int tx = threadIdx.x, ty = threadIdx.y;
    const int n0 = blockIdx.x * 32, k0 = blockIdx.y * 32;
    #pragma unroll
    for (int i = 0; i < 4; i++)
        t[ty + 8 * i][tx] = W[(size_t)(k0 + ty + 8 * i) * DIM + n0 + tx];
    __syncthreads();
    #pragma unroll
    for (int i = 0; i < 4; i++)
        o[(size_t)(n0 + ty + 8 * i) * DIM + k0 + tx] = totf(t[tx][ty + 8 * i]);
}

__global__ void prep_vT() {
    __shared__ float t[32][33];
    const int b = blockIdx.z;
    const float* V = g_V + (size_t)b * SEQ * DIM;
    float* o = g_VT + (size_t)b * DIM * SEQ;
    const int tx = threadIdx.x, ty = threadIdx.y;
    const int d0 = blockIdx.x * 32, s0 = blockIdx.y * 32;
    #pragma unroll
    for (int i = 0; i < 4; i++)
        t[ty + 8 * i][tx] = V[(size_t)(s0 + ty + 8 * i) * DIM + d0 + tx];
    __syncthreads();
    #pragma unroll
    for (int i = 0; i < 4; i++)
        o[(size_t)(d0 + ty + 8 * i) * SEQ + s0 + tx] = t[tx][ty + 8 * i];
}

// ---------------------------------------------------------------------------
// GEMM 1: QKV projection (256x128 tiles) -> tf32-rounded Q/K/V
// ---------------------------------------------------------------------------
__global__ void __launch_bounds__(NTHREADS) qkv_tf() {
    extern __shared__ uint8_t dsm[];
    const uint32_t smb = su32(dsm);
    const int tid = threadIdx.x;
    const int lane = tid & 31;
    const int wid = tid >> 5;
    const int wm = wid & 3, wn = wid >> 2;

    const int w = blockIdx.z;
    const int m0 = blockIdx.y * 256;
    const int n0 = blockIdx.x * 128;
    const float* A = g_X + (size_t)m0 * DIM;
    const float* B = g_WT + (size_t)w * DIM * DIM + (size_t)n0 * DIM;
    float* C = (w == 0) ? g_Q : (w == 1) ? g_K : g_V;

    float acc[4][4][4] = {};
    gemm_pipeline(smb, DIM / 32, A, DIM, B, DIM, acc, tid, lane, wm, wn);
    store_acc(acc, C, DIM, m0, n0, 2, lane, wm, wn);
}

// ---------------------------------------------------------------------------
// GEMM 2: scores = scale * Q @ K^T (256-row q-tiles x 128-col k-tiles)
// ---------------------------------------------------------------------------
__global__ void __launch_bounds__(NTHREADS) scores_tf() {
    const int kt = blockIdx.x;
    const int qt = blockIdx.y;
    if (kt * 128 >= (qt + 1) * 256) return;   // fully above diagonal
    extern __shared__ uint8_t dsm[];
    const uint32_t smb = su32(dsm);
    const int tid = threadIdx.x;
    const int lane = tid & 31;
    const int wid = tid >> 5;
    const int wm = wid & 3, wn = wid >> 2;

    const int b = blockIdx.z;
    const int m0 = qt * 256;
    const int n0 = kt * 128;
    const float* A = g_Q + (size_t)(b * SEQ + m0) * DIM;
    const float* B = g_K + (size_t)(b * SEQ + n0) * DIM;

    float acc[4][4][4] = {};
    gemm_pipeline(smb, DIM / 32, A, DIM, B, DIM, acc, tid, lane, wm, wn);
    store_acc(acc, g_S + (size_t)b * SEQ * SEQ, SEQ, m0, n0, 1, lane, wm, wn);
}

// ---------------------------------------------------------------------------
// Kernel 3: row softmax -> tf32-rounded P, zero-padded to 256-aligned extent
// ---------------------------------------------------------------------------
__global__ void __launch_bounds__(256) softmax_rows() {
    const int q = blockIdx.x;
    const int b = blockIdx.y;
    const size_t base = (size_t)b * SEQ * SEQ + (size_t)q * SEQ;
    const float* row = g_S + base;
    const int L  = ((q >> 7) + 1) << 7;    // normalization extent (128-aligned)
    const int Lw = ((q >> 8) + 1) << 8;    // write extent (256-aligned for PV)

    const int tid = threadIdx.x;
    __shared__ float red[256];

    float vals[8];
    int cnt = 0;
    float m = -1e30f;
    for (int idx = tid; idx < L; idx += 256) {
        vals[cnt] = row[idx];
        m = fmaxf(m, vals[cnt]);
        cnt++;
    }
    red[tid] = m;
    __syncthreads();
    #pragma unroll
    for (int s = 128; s > 0; s >>= 1) {
        if (tid < s) red[tid] = fmaxf(red[tid], red[tid + s]);
        __syncthreads();
    }
    const float M = red[0];
    __syncthreads();

    float sum = 0.f;
    for (int i = 0; i < cnt; i++) {
        vals[i] = __expf(vals[i] - M);
        sum += vals[i];
    }
    red[tid] = sum;
    __syncthreads();
    #pragma unroll
    for (int s = 128; s > 0; s >>= 1) {
        if (tid < s) red[tid] += red[tid + s];
        __syncthreads();
    }
    const float inv = 1.0f / red[0];

    cnt = 0;
    for (int idx = tid; idx < Lw; idx += 256) {
        float p = 0.0f;
        if (idx < L) p = vals[cnt++] * inv;
        g_P[base + idx] = totf(p);
    }
}

// ---------------------------------------------------------------------------
// GEMM 4: O = P @ V (256-row q-tiles), causal K-extent, heavy q-tiles first
// ---------------------------------------------------------------------------
__global__ void __launch_bounds__(NTHREADS) pv_tf(float* __restrict__ out) {
    extern __shared__ uint8_t dsm[];
    const uint32_t smb = su32(dsm);
    const int tid = threadIdx.x;
    const int lane = tid & 31;
    const int wid = tid >> 5;
    const int wm = wid & 3, wn = wid >> 2;

    const int et = blockIdx.x;
    const int qt = (SEQ / 256 - 1) - blockIdx.y;   // heavy tiles first
    const int b  = blockIdx.z;
    const int m0 = qt * 256;
    const int n0 = et * 128;
    const int nchunks = (qt + 1) * 8;   // K-extent (qt+1)*256 / 32

    const float* A = g_P + (size_t)b * SEQ * SEQ + (size_t)m0 * SEQ;
    const float* B = g_VT + (size_t)b * DIM * SEQ + (size_t)n0 * SEQ;

    float acc[4][4][4] = {};
    gemm_pipeline(smb, nchunks, A, SEQ, B, SEQ, acc, tid, lane, wm, wn);
    store_acc(acc, out + (size_t)b * SEQ * DIM, DIM, m0, n0, 0, lane, wm, wn);
}

// ---------------------------------------------------------------------------
extern "C" void kernel_launch(void* const* d_in, const int* in_sizes, int n_in,
                              void* d_out, int out_size) {
    const float* x  = (const float*)d_in[0];
    const float* Wq = (const float*)d_in[1];
    const float* Wk = (const float*)d_in[2];
    const float* Wv = (const float*)d_in[3];
    float* out = (float*)d_out;

    const int DSM = NSTAGE * STAGE_BYTES;  // 144KB, 1 CTA/SM
    static bool attr_done = false;
    if (!attr_done) {
        cudaFuncSetAttribute(qkv_tf, cudaFuncAttributeMaxDynamicSharedMemorySize, DSM);
        cudaFuncSetAttribute(scores_tf, cudaFuncAttributeMaxDynamicSharedMemorySize, DSM);
        cudaFuncSetAttribute(pv_tf, cudaFuncAttributeMaxDynamicSharedMemorySize, DSM);
        attr_done = true;
    }

    round_x<<<(MTOT * DIM / 4) / 256, 256>>>((const float4*)x);
    prep_w<<<dim3(DIM / 32, DIM / 32, 3), dim3(32, 8)>>>(Wq, Wk, Wv);
    qkv_tf<<<dim3(DIM / 128, MTOT / 256, 3), NTHREADS, DSM>>>();
    prep_vT<<<dim3(DIM / 32, SEQ / 32, BATCH), dim3(32, 8)>>>();
    scores_tf<<<dim3(SEQ / 128, SEQ / 256, BATCH), NTHREADS, DSM>>>();
    softmax_rows<<<dim3(SEQ, BATCH), 256>>>();
    pv_tf<<<dim3(DIM / 128, SEQ / 256, BATCH), NTHREADS, DSM>>>(out);
}